// round 14
// baseline (speedup 1.0000x reference)
#include <cuda_runtime.h>
#include <math.h>
#include <stdint.h>

#define NB      2
#define S_LEN   4096
#define BS_TOT  8192
#define E_DIM   640
#define H_Q     4
#define D_HEAD  256
#define HD      1024
#define WIN     512
#define SCALE_F 0.0625f   // 256^-0.5, exact power of 2

// ---------------- scratch ----------------
__device__ float g_q  [(size_t)BS_TOT * HD];
__device__ float g_k  [(size_t)BS_TOT * D_HEAD];
__device__ float g_vT [(size_t)D_HEAD * BS_TOT];   // transposed V: [d][b*S+s]
__device__ float g_ao [(size_t)BS_TOT * HD];
// tf32-pre-rounded copies of GEMM inputs
__device__ float g_x  [(size_t)BS_TOT * E_DIM];
__device__ float g_wq [(size_t)E_DIM * HD];
__device__ float g_wk [(size_t)E_DIM * D_HEAD];
__device__ float g_wv [(size_t)E_DIM * D_HEAD];
__device__ float g_wo [(size_t)HD * E_DIM];

__device__ __forceinline__ uint32_t f2tf32(float x) {
    uint32_t r;
    asm("cvt.rna.tf32.f32 %0, %1;" : "=r"(r) : "f"(x));
    return r;
}
__device__ __forceinline__ float tf(float x) { return __uint_as_float(f2tf32(x)); }
__device__ __forceinline__ uint32_t smem_u32(const void* p) {
    uint32_t a;
    asm("{ .reg .u64 t; cvta.to.shared.u64 t, %1; cvt.u32.u64 %0, t; }" : "=r"(a) : "l"(p));
    return a;
}
__device__ __forceinline__ void cp16(uint32_t s, const void* g) {
    asm volatile("cp.async.cg.shared.global [%0], [%1], 16;" :: "r"(s), "l"(g));
}

#define MMA8(c, a0,a1,a2,a3, b0,b1) \
    asm volatile("mma.sync.aligned.m16n8k8.row.col.f32.tf32.tf32.f32 " \
        "{%0,%1,%2,%3}, {%4,%5,%6,%7}, {%8,%9}, {%0,%1,%2,%3};" \
        : "+f"(c[0]), "+f"(c[1]), "+f"(c[2]), "+f"(c[3]) \
        : "r"(a0), "r"(a1), "r"(a2), "r"(a3), "r"(b0), "r"(b1))

// ---------------- prep: round x + weights to tf32 once ----------------
#define X_F4   ((BS_TOT * E_DIM) / 4)
#define WQ_F4  ((E_DIM * HD) / 4)
#define WK_F4  ((E_DIM * D_HEAD) / 4)
#define WO_F4  ((HD * E_DIM) / 4)
#define TOT_F4 (X_F4 + WQ_F4 + 2 * WK_F4 + WO_F4)

__global__ void prep_round(const float4* __restrict__ x,  const float4* __restrict__ wq,
                           const float4* __restrict__ wk, const float4* __restrict__ wv,
                           const float4* __restrict__ wo) {
    for (int i = blockIdx.x * blockDim.x + threadIdx.x; i < TOT_F4; i += gridDim.x * blockDim.x) {
        const float4* src; float4* dst; int j = i;
        if (j < X_F4)                { src = x;  dst = (float4*)g_x;  }
        else if ((j -= X_F4)  < WQ_F4) { src = wq; dst = (float4*)g_wq; }
        else if ((j -= WQ_F4) < WK_F4) { src = wk; dst = (float4*)g_wk; }
        else if ((j -= WK_F4) < WK_F4) { src = wv; dst = (float4*)g_wv; }
        else  { j -= WK_F4;            src = wo; dst = (float4*)g_wo; }
        float4 v = src[j];
        v.x = tf(v.x); v.y = tf(v.y); v.z = tf(v.z); v.w = tf(v.w);
        dst[j] = v;
    }
}

// =========== cp.async 2-stage tf32 GEMM core (pre-rounded inputs) ===========
// Block tile 128x128, K-chunk 32, 128 threads = 4 warps (2x2), each warp 64x64
// (4 m-atoms x 8 n-atoms). 3 CTAs/SM.
#define AS_STRIDE 36
#define BS_STRIDE 132
#define STG_FLTS  (128 * AS_STRIDE + 32 * BS_STRIDE)   // 8832 floats per stage
#define GEMM_SMEM (2 * STG_FLTS * 4)                   // 70656 bytes

__device__ __forceinline__ void cp_stage(const float* __restrict__ A,
                                         const float* __restrict__ B,
                                         int N, int K, int bm, int bn, int k0,
                                         uint32_t sa, int tid) {
    uint32_t sb = sa + 128 * AS_STRIDE * 4;
    #pragma unroll
    for (int i = 0; i < 8; i++) {
        int idx = tid + i * 128;
        int r = idx >> 3, c4 = idx & 7;
        cp16(sa + (uint32_t)(r * AS_STRIDE + c4 * 4) * 4,
             &A[(size_t)(bm + r) * K + k0 + c4 * 4]);
    }
    #pragma unroll
    for (int i = 0; i < 8; i++) {
        int idx = tid + i * 128;
        int r = idx >> 5, c4 = idx & 31;
        cp16(sb + (uint32_t)(r * BS_STRIDE + c4 * 4) * 4,
             &B[(size_t)(k0 + r) * N + bn + c4 * 4]);
    }
}

__device__ __forceinline__ void gemm_core(const float* __restrict__ A,
                                          const float* __restrict__ B,
                                          float* __restrict__ C,
                                          int M, int N, int K,
                                          int bm, int bn, int transC,
                                          float* dsm) {
    int tid = threadIdx.x, lane = tid & 31, wid = tid >> 5;
    int wm = wid & 1, wn = wid >> 1;            // 64-row slab, 64-col slab
    int gid = lane >> 2, tig = lane & 3;
    uint32_t sbase = smem_u32(dsm);

    float acc[4][8][4];
    #pragma unroll
    for (int i = 0; i < 4; i++)
        #pragma unroll
        for (int j = 0; j < 8; j++)
            #pragma unroll
            for (int r = 0; r < 4; r++) acc[i][j][r] = 0.f;

    int kc = K / 32;

    cp_stage(A, B, N, K, bm, bn, 0, sbase, tid);
    asm volatile("cp.async.commit_group;");

    for (int ch = 0; ch < kc; ch++) {
        if (ch + 1 < kc) {
            cp_stage(A, B, N, K, bm, bn, (ch + 1) * 32,
                     sbase + (uint32_t)((ch + 1) & 1) * STG_FLTS * 4, tid);
            asm volatile("cp.async.commit_group;");
            asm volatile("cp.async.wait_group 1;");
        } else {
            asm volatile("cp.async.wait_group 0;");
        }
        __syncthreads();

        const float* Asf = dsm + (ch & 1) * STG_FLTS;
        const float* Bsf = Asf + 128 * AS_STRIDE;

        #pragma unroll
        for (int ks = 0; ks < 4; ks++) {
            int kk = ks * 8;
            uint32_t af[4][4], bf[8][2];
            #pragma unroll
            for (int ma = 0; ma < 4; ma++) {
                const float* ab = &Asf[(wm * 64 + ma * 16) * AS_STRIDE + kk];
                af[ma][0] = __float_as_uint(ab[gid * AS_STRIDE + tig]);
                af[ma][1] = __float_as_uint(ab[(gid + 8) * AS_STRIDE + tig]);
                af[ma][2] = __float_as_uint(ab[gid * AS_STRIDE + tig + 4]);
                af[ma][3] = __float_as_uint(ab[(gid + 8) * AS_STRIDE + tig + 4]);
            }
            #pragma unroll
            for (int na = 0; na < 8; na++) {
                const float* bb = &Bsf[kk * BS_STRIDE + wn * 64 + na * 8 + gid];
                bf[na][0] = __float_as_uint(bb[tig * BS_STRIDE]);
                bf[na][1] = __float_as_uint(bb[(tig + 4) * BS_STRIDE]);
            }
            #pragma unroll
            for (int ma = 0; ma < 4; ma++)
                #pragma unroll
                for (int na = 0; na < 8; na++)
                    MMA8(acc[ma][na], af[ma][0], af[ma][1], af[ma][2], af[ma][3],
                         bf[na][0], bf[na][1]);
        }
        __syncthreads();
    }

    if (!transC) {
        #pragma unroll
        for (int ma = 0; ma < 4; ma++) {
            int r0 = bm + wm * 64 + ma * 16 + gid;
            #pragma unroll
            for (int na = 0; na < 8; na++) {
                int cc = bn + wn * 64 + na * 8 + tig * 2;
                float* c = acc[ma][na];
                *reinterpret_cast<float2*>(&C[(size_t)r0 * N + cc])       = make_float2(c[0], c[1]);
                *reinterpret_cast<float2*>(&C[(size_t)(r0 + 8) * N + cc]) = make_float2(c[2], c[3]);
            }
        }
    } else {
        // transposed epilogue: C^T[N][M], tf32-rounded (feeds attention), smem-staged
        float* tbuf = dsm;   // 32 x 132
        for (int p = 0; p < 4; p++) {
            __syncthreads();
            if (wn == (p >> 1)) {
                int na0 = (p & 1) * 4;
                #pragma unroll
                for (int na = 0; na < 4; na++) {
                    int ccl = (na0 + na) * 8 + 2 * tig - (p & 1) * 32;
                    #pragma unroll
                    for (int ma = 0; ma < 4; ma++) {
                        int r = wm * 64 + ma * 16 + gid;
                        float* c = acc[ma][na0 + na];
                        tbuf[ccl * 132 + r]           = tf(c[0]);
                        tbuf[(ccl + 1) * 132 + r]     = tf(c[1]);
                        tbuf[ccl * 132 + r + 8]       = tf(c[2]);
                        tbuf[(ccl + 1) * 132 + r + 8] = tf(c[3]);
                    }
                }
            }
            __syncthreads();
            for (int i = tid; i < 32 * 32; i += 128) {
                int rr = i >> 5, c4 = i & 31;
                float4 v = *reinterpret_cast<float4*>(&tbuf[rr * 132 + c4 * 4]);
                *reinterpret_cast<float4*>(&C[(size_t)(bn + p * 32 + rr) * M + bm + c4 * 4]) = v;
            }
        }
    }
}

// fused QKV: grid (12, 64). nbx 0-7 -> Wq, 8-9 -> Wk, 10-11 -> Wv (transposed out)
__global__ void __launch_bounds__(128, 3) qkv_gemm() {
    extern __shared__ float dsm[];
    int nbx = blockIdx.x;
    int bm = blockIdx.y * 128;
    if (nbx < 8) {
        gemm_core(g_x, g_wq, g_q, BS_TOT, HD, E_DIM, bm, nbx * 128, 0, dsm);
    } else if (nbx < 10) {
        gemm_core(g_x, g_wk, g_k, BS_TOT, D_HEAD, E_DIM, bm, (nbx - 8) * 128, 0, dsm);
    } else {
        gemm_core(g_x, g_wv, g_vT, BS_TOT, D_HEAD, E_DIM, bm, (nbx - 10) * 128, 1, dsm);
    }
}

__global__ void __launch_bounds__(128, 3) wo_gemm(float* __restrict__ out) {
    extern __shared__ float dsm[];
    gemm_core(g_ao, g_wo, out, BS_TOT, E_DIM, HD, blockIdx.y * 128, blockIdx.x * 128, 0, dsm);
}

// ---------------- fused RMSNorm + RoPE (in place, emits tf32-rounded) ----------------
__global__ void norm_rope_kernel(const float* __restrict__ cosb, const float* __restrict__ sinb,
                                 const float* __restrict__ qw, const float* __restrict__ kw) {
    int bs = blockIdx.x;
    int which = blockIdx.y;
    int s = bs & (S_LEN - 1);
    float* row;
    const float* w;
    if (which < H_Q) { row = g_q + (size_t)bs * HD + which * D_HEAD; w = qw; }
    else             { row = g_k + (size_t)bs * D_HEAD;             w = kw; }

    int p = threadIdx.x;
    float a = row[2 * p], b = row[2 * p + 1];
    float ss = a * a + b * b;
    #pragma unroll
    for (int off = 16; off; off >>= 1) ss += __shfl_xor_sync(0xffffffffu, ss, off);
    __shared__ float red[4];
    int lane = p & 31, wid = p >> 5;
    if (lane == 0) red[wid] = ss;
    __syncthreads();
    float tot = red[0] + red[1] + red[2] + red[3];
    float inv = rsqrtf(tot * (1.0f / D_HEAD) + 1e-6f);

    float na = a * inv * (1.0f + w[2 * p]);
    float nb = b * inv * (1.0f + w[2 * p + 1]);
    float c  = cosb[(size_t)s * (D_HEAD / 2) + p];
    float sn = sinb[(size_t)s * (D_HEAD / 2) + p];
    row[2 * p]     = tf(na * c - nb * sn);
    row[2 * p + 1] = tf(na * sn + nb * c);
}

// ---------------- flash-style sliding-window MQA attention (tf32 mma) ----------------
#define QS_STR 260
#define VT_STR 68
#define PS_STR 68
#define ATTN_SMEM ((64 * QS_STR + 64 * QS_STR + 256 * VT_STR + 64 * PS_STR) * 4)

__global__ void __launch_bounds__(128, 1) attn_mma() {
    extern __shared__ float sm[];
    float* Qs  = sm;                       // 64 x 260
    float* Ks  = Qs + 64 * QS_STR;         // 64 x 260
    float* VsT = Ks + 64 * QS_STR;         // 256 x 68
    float* Ps  = VsT + 256 * VT_STR;       // 64 x 68

    int tid = threadIdx.x, lane = tid & 31, w = tid >> 5;
    int gid = lane >> 2, tig = lane & 3;
    int qc = blockIdx.x, b = blockIdx.y, h = blockIdx.z;
    int qs = qc * 64;

    for (int i = tid; i < 64 * 64; i += 128) {
        int r = i >> 6, c4 = i & 63;
        float4 v = *reinterpret_cast<const float4*>(
            &g_q[(size_t)(b * S_LEN + qs + r) * HD + h * D_HEAD + c4 * 4]);
        float* d = &Qs[r * QS_STR + c4 * 4];
        d[0] = v.x * SCALE_F; d[1] = v.y * SCALE_F;
        d[2] = v.z * SCALE_F; d[3] = v.w * SCALE_F;
    }

    float acc[32][4];
    #pragma unroll
    for (int na = 0; na < 32; na++)
        #pragma unroll
        for (int e = 0; e < 4; e++) acc[na][e] = 0.f;
    float m0 = -1e30f, m1 = -1e30f, l0 = 0.f, l1 = 0.f;

    int r0 = w * 16 + gid, r1 = r0 + 8;
    int i0 = qs + r0, i1 = qs + r1;
    int clo = (qc >= 8) ? qc - 8 : 0;

    for (int c = clo; c <= qc; c++) {
        int kstart = c * 64;
        __syncthreads();
        for (int i = tid; i < 64 * 64; i += 128) {
            int r = i >> 6, c4 = i & 63;
            float4 v = *reinterpret_cast<const float4*>(
                &g_k[(size_t)(b * S_LEN + kstart + r) * D_HEAD + c4 * 4]);
            float* d = &Ks[r * QS_STR + c4 * 4];
            d[0] = v.x; d[1] = v.y; d[2] = v.z; d[3] = v.w;
        }
        for (int i = tid; i < 256 * 16; i += 128) {
            int dd = i >> 4, j4 = i & 15;
            float4 v = *reinterpret_cast<const float4*>(
                &g_vT[(size_t)dd * BS_TOT + b * S_LEN + kstart + j4 * 4]);
            float* d = &VsT[dd * VT_STR + j4 * 4];
            d[0] = v.x; d[1] = v.y; d[2] = v.z; d[3] = v.w;
        }
        __syncthreads();

        float s[8][4];
        #pragma unroll
        for (int na = 0; na < 8; na++)
            #pragma unroll
            for (int e = 0; e < 4; e++) s[na][e] = 0.f;

        #pragma unroll
        for (int ks = 0; ks < 32; ks++) {
            int kk = ks * 8;
            const float* ab = &Qs[r0 * QS_STR + kk];
            uint32_t a0 = __float_as_uint(ab[tig]);
            uint32_t a1 = __float_as_uint(ab[8 * QS_STR + tig]);
            uint32_t a2 = __float_as_uint(ab[tig + 4]);
            uint32_t a3 = __float_as_uint(ab[8 * QS_STR + tig + 4]);
            #pragma unroll
            for (int na = 0; na < 8; na++) {
                const float* bb = &Ks[(na * 8 + gid) * QS_STR + kk];
                uint32_t b0 = __float_as_uint(bb[tig]);
                uint32_t b1 = __float_as_uint(bb[tig + 4]);
                MMA8(s[na], a0, a1, a2, a3, b0, b1);
            }
        }

        if (c == qc || c == qc - 8) {
            #pragma unroll
            for (int na = 0; na < 8; na++) {
                int j0 = kstart + na * 8 + 2 * tig;
                #pragma unroll
                for (int e = 0; e < 4; e++) {
                    int j = j0 + (e & 1);
                    int i = (e < 2) ? i0 : i1;
                    if (j > i || i - j > WIN) s[na][e] = -1e30f;
                }
            }
        }

        float mx0 = -1e30f, mx1 = -1e30f;
        #pragma unroll
        for (int na = 0; na < 8; na++) {
            mx0 = fmaxf(mx0, fmaxf(s[na][0], s[na][1]));
            mx1 = fmaxf(mx1, fmaxf(s[na][2], s[na][3]));
        }
        mx0 = fmaxf(mx0, __shfl_xor_sync(0xffffffffu, mx0, 1));
        mx0 = fmaxf(mx0, __shfl_xor_sync(0xffffffffu, mx0, 2));
        mx1 = fmaxf(mx1, __shfl_xor_sync(0xffffffffu, mx1, 1));
        mx1 = fmaxf(mx1, __shfl_xor_sync(0xffffffffu, mx1, 2));

        float mn0 = fmaxf(m0, mx0), mn1 = fmaxf(m1, mx1);
        float al0 = __expf(m0 - mn0), al1 = __expf(m1 - mn1);
        m0 = mn0; m1 = mn1;

        float sum0 = 0.f, sum1 = 0.f;
        #pragma unroll
        for (int na = 0; na < 8; na++) {
            float p00 = __expf(s[na][0] - m0);
            float p01 = __expf(s[na][1] - m0);
            float p10 = __expf(s[na][2] - m1);
            float p11 = __expf(s[na][3] - m1);
            sum0 += p00 + p01; sum1 += p10 + p11;
            int cc = na * 8 + 2 * tig;
            *reinterpret_cast<float2*>(&Ps[r0 * PS_STR + cc]) =
                make_float2(__uint_as_float(f2tf32(p00)), __uint_as_float(f2tf32(p01)));
            *reinterpret_cast<float2*>(&Ps[r1 * PS_STR + cc]) =
                make_float2(__uint_as_float(f2tf32(p10)), __uint_as_float(f2tf32(p11)));
        }
        sum0 += __shfl_xor_sync(0xffffffffu, sum0, 1);
        sum0 += __shfl_xor_sync(0xffffffffu, sum0, 2);
        sum1 += __shfl_xor_sync(0xffffffffu, sum1, 1);
        sum1 += __shfl_xor_sync(0xffffffffu, sum1, 2);
        l0 = l0 * al0 + sum0;
        l1 = l1 * al1 + sum1;

        #pragma unroll
        for (int na = 0; na < 32; na++) {
            acc[na][0] *= al0; acc[na][1] *= al0;
            acc[na][2] *= al1; acc[na][3] *= al1;
        }
        __syncwarp();

        #pragma unroll
        for (int ks = 0; ks < 8; ks++) {
            int kk = ks * 8;
            const float* ab = &Ps[r0 * PS_STR + kk];
            uint32_t a0 = __float_as_uint(ab[tig]);
            uint32_t a1 = __float_as_uint(ab[8 * PS_STR + tig]);
            uint32_t a2 = __float_as_uint(ab[tig + 4]);
            uint32_t a3 = __float_as_uint(ab[8 * PS_STR + tig + 4]);
            #pragma unroll
            for (int na = 0; na < 32; na++) {
                const float* bb = &VsT[(na * 8 + gid) * VT_STR + kk];
                uint32_t b0 = __float_as_uint(bb[tig]);
                uint32_t b1 = __float_as_uint(bb[tig + 4]);
                MMA8(acc[na], a0, a1, a2, a3, b0, b1);
            }
        }
    }

    // epilogue: tf32-rounded (g_ao feeds the Wo GEMM directly)
    float inv0 = 1.0f / l0, inv1 = 1.0f / l1;
    size_t base0 = (size_t)(b * S_LEN + qs + r0) * HD + h * D_HEAD;
    size_t base1 = (size_t)(b * S_LEN + qs + r1) * HD + h * D_HEAD;
    #pragma unroll
    for (int na = 0; na < 32; na++) {
        int cc = na * 8 + 2 * tig;
        *reinterpret_cast<float2*>(&g_ao[base0 + cc]) =
            make_float2(tf(acc[na][0] * inv0), tf(acc[na][1] * inv0));
        *reinterpret_cast<float2*>(&g_ao[base1 + cc]) =
            make_float2(tf(acc[na][2] * inv1), tf(acc[na][3] * inv1));
    }
}

// ---------------- launch ----------------
extern "C" void kernel_launch(void* const* d_in, const int* in_sizes, int n_in,
                              void* d_out, int out_size) {
    const float* x    = (const float*)d_in[0];
    const float* cosb = (const float*)d_in[1];
    const float* sinb = (const float*)d_in[2];
    const float* Wq   = (const float*)d_in[3];
    const float* Wk   = (const float*)d_in[4];
    const float* Wv   = (const float*)d_in[5];
    const float* Wo   = (const float*)d_in[6];
    const float* qw   = (const float*)d_in[7];
    const float* kw   = (const float*)d_in[8];
    float* out = (float*)d_out;

    static int smem_set = 0;
    if (!smem_set) {
        cudaFuncSetAttribute(attn_mma, cudaFuncAttributeMaxDynamicSharedMemorySize, ATTN_SMEM);
        cudaFuncSetAttribute(qkv_gemm, cudaFuncAttributeMaxDynamicSharedMemorySize, GEMM_SMEM);
        cudaFuncSetAttribute(wo_gemm,  cudaFuncAttributeMaxDynamicSharedMemorySize, GEMM_SMEM);
        smem_set = 1;
    }

    prep_round<<<1024, 256>>>((const float4*)x, (const float4*)Wq, (const float4*)Wk,
                              (const float4*)Wv, (const float4*)Wo);

    qkv_gemm<<<dim3(12, BS_TOT / 128), 128, GEMM_SMEM>>>();

    norm_rope_kernel<<<dim3(BS_TOT, H_Q + 1), 128>>>(cosb, sinb, qw, kw);

    attn_mma<<<dim3(S_LEN / 64, NB, H_Q), 128, ATTN_SMEM>>>();

    wo_gemm<<<dim3(E_DIM / 128, BS_TOT / 128), 128, GEMM_SMEM>>>(out);
}

// round 17
// speedup vs baseline: 1.4359x; 1.4359x over previous
#include <cuda_runtime.h>
#include <math.h>
#include <stdint.h>

#define NB      2
#define S_LEN   4096
#define BS_TOT  8192
#define E_DIM   640
#define H_Q     4
#define D_HEAD  256
#define HD      1024
#define WIN     512
#define SCALE_F 0.0625f   // 256^-0.5, exact power of 2

// ---------------- scratch ----------------
__device__ float g_q  [(size_t)BS_TOT * HD];
__device__ float g_k  [(size_t)BS_TOT * D_HEAD];
__device__ float g_vT [(size_t)D_HEAD * BS_TOT];   // transposed V: [d][b*S+s]
__device__ float g_ao [(size_t)BS_TOT * HD];

__device__ __forceinline__ uint32_t f2tf32(float x) {
    uint32_t r;
    asm("cvt.rna.tf32.f32 %0, %1;" : "=r"(r) : "f"(x));
    return r;
}
__device__ __forceinline__ float tf(float x) { return __uint_as_float(f2tf32(x)); }

#define MMA8(c, a0,a1,a2,a3, b0,b1) \
    asm volatile("mma.sync.aligned.m16n8k8.row.col.f32.tf32.tf32.f32 " \
        "{%0,%1,%2,%3}, {%4,%5,%6,%7}, {%8,%9}, {%0,%1,%2,%3};" \
        : "+f"(c[0]), "+f"(c[1]), "+f"(c[2]), "+f"(c[3]) \
        : "r"(a0), "r"(a1), "r"(a2), "r"(a3), "r"(b0), "r"(b1))

// =========== register-prefetch double-buffered tf32 GEMM core (R11 winner) ====
// Block tile 128x128, K-chunk 32, 256 threads = 8 warps of 32x64, cvt at STS.
#define AS_STRIDE 36
#define BS_STRIDE 132
#define STG_FLTS  (128 * AS_STRIDE + 32 * BS_STRIDE)   // 8832 floats per stage
#define GEMM_SMEM (2 * STG_FLTS * 4)                   // 70656 bytes

__device__ __forceinline__ void gemm_core(const float* __restrict__ A,
                                          const float* __restrict__ B,
                                          float* __restrict__ C,
                                          int M, int N, int K,
                                          int bm, int bn, int transC,
                                          float* dsm) {
    int tid = threadIdx.x, lane = tid & 31, wid = tid >> 5;
    int wm = wid & 3, wn = wid >> 2;
    int gid = lane >> 2, tig = lane & 3;

    float acc[2][8][4];
    #pragma unroll
    for (int i = 0; i < 2; i++)
        #pragma unroll
        for (int j = 0; j < 8; j++)
            #pragma unroll
            for (int r = 0; r < 4; r++) acc[i][j][r] = 0.f;

    int kc = K / 32;

    float4 ra[4], rb[4];
    #pragma unroll
    for (int i = 0; i < 4; i++) {
        int idx = tid + i * 256;
        int r = idx >> 3, c4 = idx & 7;
        ra[i] = *reinterpret_cast<const float4*>(&A[(size_t)(bm + r) * K + c4 * 4]);
    }
    #pragma unroll
    for (int i = 0; i < 4; i++) {
        int idx = tid + i * 256;
        int r = idx >> 5, c4 = idx & 31;
        rb[i] = *reinterpret_cast<const float4*>(&B[(size_t)r * N + bn + c4 * 4]);
    }

    for (int ch = 0; ch < kc; ch++) {
        float* Asf = dsm + (ch & 1) * STG_FLTS;
        float* Bsf = Asf + 128 * AS_STRIDE;

        #pragma unroll
        for (int i = 0; i < 4; i++) {
            int idx = tid + i * 256;
            int r = idx >> 3, c4 = idx & 7;
            float* d = &Asf[r * AS_STRIDE + c4 * 4];
            d[0] = tf(ra[i].x); d[1] = tf(ra[i].y); d[2] = tf(ra[i].z); d[3] = tf(ra[i].w);
        }
        #pragma unroll
        for (int i = 0; i < 4; i++) {
            int idx = tid + i * 256;
            int r = idx >> 5, c4 = idx & 31;
            float* d = &Bsf[r * BS_STRIDE + c4 * 4];
            d[0] = tf(rb[i].x); d[1] = tf(rb[i].y); d[2] = tf(rb[i].z); d[3] = tf(rb[i].w);
        }
        __syncthreads();

        if (ch + 1 < kc) {
            int k0 = (ch + 1) * 32;
            #pragma unroll
            for (int i = 0; i < 4; i++) {
                int idx = tid + i * 256;
                int r = idx >> 3, c4 = idx & 7;
                ra[i] = *reinterpret_cast<const float4*>(&A[(size_t)(bm + r) * K + k0 + c4 * 4]);
            }
            #pragma unroll
            for (int i = 0; i < 4; i++) {
                int idx = tid + i * 256;
                int r = idx >> 5, c4 = idx & 31;
                rb[i] = *reinterpret_cast<const float4*>(&B[(size_t)(k0 + r) * N + bn + c4 * 4]);
            }
        }

        #pragma unroll
        for (int ks = 0; ks < 4; ks++) {
            int kk = ks * 8;
            uint32_t af[2][4], bf[8][2];
            #pragma unroll
            for (int ma = 0; ma < 2; ma++) {
                const float* ab = &Asf[(wm * 32 + ma * 16) * AS_STRIDE + kk];
                af[ma][0] = __float_as_uint(ab[gid * AS_STRIDE + tig]);
                af[ma][1] = __float_as_uint(ab[(gid + 8) * AS_STRIDE + tig]);
                af[ma][2] = __float_as_uint(ab[gid * AS_STRIDE + tig + 4]);
                af[ma][3] = __float_as_uint(ab[(gid + 8) * AS_STRIDE + tig + 4]);
            }
            #pragma unroll
            for (int na = 0; na < 8; na++) {
                const float* bb = &Bsf[kk * BS_STRIDE + wn * 64 + na * 8 + gid];
                bf[na][0] = __float_as_uint(bb[tig * BS_STRIDE]);
                bf[na][1] = __float_as_uint(bb[(tig + 4) * BS_STRIDE]);
            }
            #pragma unroll
            for (int ma = 0; ma < 2; ma++)
                #pragma unroll
                for (int na = 0; na < 8; na++)
                    MMA8(acc[ma][na], af[ma][0], af[ma][1], af[ma][2], af[ma][3],
                         bf[na][0], bf[na][1]);
        }
    }

    if (!transC) {
        #pragma unroll
        for (int ma = 0; ma < 2; ma++) {
            int r0 = bm + wm * 32 + ma * 16 + gid;
            #pragma unroll
            for (int na = 0; na < 8; na++) {
                int cc = bn + wn * 64 + na * 8 + tig * 2;
                float* c = acc[ma][na];
                *reinterpret_cast<float2*>(&C[(size_t)r0 * N + cc])       = make_float2(c[0], c[1]);
                *reinterpret_cast<float2*>(&C[(size_t)(r0 + 8) * N + cc]) = make_float2(c[2], c[3]);
            }
        }
    } else {
        float* tbuf = dsm;   // 32 x 132
        for (int p = 0; p < 4; p++) {
            __syncthreads();
            if (wn == (p >> 1)) {
                int na0 = (p & 1) * 4;
                #pragma unroll
                for (int na = 0; na < 4; na++) {
                    int ccl = (na0 + na) * 8 + 2 * tig - (p & 1) * 32;
                    #pragma unroll
                    for (int ma = 0; ma < 2; ma++) {
                        int r = wm * 32 + ma * 16 + gid;
                        float* c = acc[ma][na0 + na];
                        tbuf[ccl * 132 + r]           = c[0];
                        tbuf[(ccl + 1) * 132 + r]     = c[1];
                        tbuf[ccl * 132 + r + 8]       = c[2];
                        tbuf[(ccl + 1) * 132 + r + 8] = c[3];
                    }
                }
            }
            __syncthreads();
            for (int i = tid; i < 32 * 32; i += 256) {
                int rr = i >> 5, c4 = i & 31;
                float4 v = *reinterpret_cast<float4*>(&tbuf[rr * 132 + c4 * 4]);
                *reinterpret_cast<float4*>(&C[(size_t)(bn + p * 32 + rr) * M + bm + c4 * 4]) = v;
            }
        }
    }
}

// fused QKV: grid (12, 64). nbx 0-7 -> Wq, 8-9 -> Wk, 10-11 -> Wv (transposed out)
__global__ void __launch_bounds__(256, 1) qkv_gemm(const float* __restrict__ x,
                                                   const float* __restrict__ Wq,
                                                   const float* __restrict__ Wk,
                                                   const float* __restrict__ Wv) {
    extern __shared__ float dsm[];
    int nbx = blockIdx.x;
    int bm = blockIdx.y * 128;
    if (nbx < 8) {
        gemm_core(x, Wq, g_q, BS_TOT, HD, E_DIM, bm, nbx * 128, 0, dsm);
    } else if (nbx < 10) {
        gemm_core(x, Wk, g_k, BS_TOT, D_HEAD, E_DIM, bm, (nbx - 8) * 128, 0, dsm);
    } else {
        gemm_core(x, Wv, g_vT, BS_TOT, D_HEAD, E_DIM, bm, (nbx - 10) * 128, 1, dsm);
    }
}

__global__ void __launch_bounds__(256, 1) wo_gemm(const float* __restrict__ Wo,
                                                  float* __restrict__ out) {
    extern __shared__ float dsm[];
    gemm_core(g_ao, Wo, out, BS_TOT, E_DIM, HD, blockIdx.y * 128, blockIdx.x * 128, 0, dsm);
}

// ---------------- fused RMSNorm + RoPE (in place on g_q / g_k) ----------------
__global__ void norm_rope_kernel(const float* __restrict__ cosb, const float* __restrict__ sinb,
                                 const float* __restrict__ qw, const float* __restrict__ kw) {
    int bs = blockIdx.x;
    int which = blockIdx.y;
    int s = bs & (S_LEN - 1);
    float* row;
    const float* w;
    if (which < H_Q) { row = g_q + (size_t)bs * HD + which * D_HEAD; w = qw; }
    else             { row = g_k + (size_t)bs * D_HEAD;             w = kw; }

    int p = threadIdx.x;
    float a = row[2 * p], b = row[2 * p + 1];
    float ss = a * a + b * b;
    #pragma unroll
    for (int off = 16; off; off >>= 1) ss += __shfl_xor_sync(0xffffffffu, ss, off);
    __shared__ float red[4];
    int lane = p & 31, wid = p >> 5;
    if (lane == 0) red[wid] = ss;
    __syncthreads();
    float tot = red[0] + red[1] + red[2] + red[3];
    float inv = rsqrtf(tot * (1.0f / D_HEAD) + 1e-6f);

    float na = a * inv * (1.0f + w[2 * p]);
    float nb = b * inv * (1.0f + w[2 * p + 1]);
    float c  = cosb[(size_t)s * (D_HEAD / 2) + p];
    float sn = sinb[(size_t)s * (D_HEAD / 2) + p];
    row[2 * p]     = na * c - nb * sn;
    row[2 * p + 1] = na * sn + nb * c;
}

// ---------------- flash-style sliding-window MQA attention (tf32 mma) ----------------
// Block = (128-query tile, batch, head). 256 threads = 8 warps (16 rows each).
// K/V processed in 32-key chunks.
#define QS_STR 260
#define KS_STR 260
#define VT_STR 36
#define PS_STR 36
#define ATTN_SMEM ((128 * QS_STR + 32 * KS_STR + 256 * VT_STR + 128 * PS_STR) * 4)

__global__ void __launch_bounds__(256, 1) attn_mma() {
    extern __shared__ float sm[];
    float* Qs  = sm;                       // 128 x 260
    float* Ks  = Qs + 128 * QS_STR;        // 32 x 260
    float* VsT = Ks + 32 * KS_STR;         // 256 x 36
    float* Ps  = VsT + 256 * VT_STR;       // 128 x 36

    int tid = threadIdx.x, lane = tid & 31, w = tid >> 5;
    int gid = lane >> 2, tig = lane & 3;
    int qt = blockIdx.x, b = blockIdx.y, h = blockIdx.z;
    int qs = qt * 128;

    // stage Q tile (scale folded, tf32)
    for (int i = tid; i < 128 * 64; i += 256) {
        int r = i >> 6, c4 = i & 63;
        float4 v = *reinterpret_cast<const float4*>(
            &g_q[(size_t)(b * S_LEN + qs + r) * HD + h * D_HEAD + c4 * 4]);
        float* d = &Qs[r * QS_STR + c4 * 4];
        d[0] = tf(v.x * SCALE_F); d[1] = tf(v.y * SCALE_F);
        d[2] = tf(v.z * SCALE_F); d[3] = tf(v.w * SCALE_F);
    }

    float acc[32][4];
    #pragma unroll
    for (int na = 0; na < 32; na++)
        #pragma unroll
        for (int e = 0; e < 4; e++) acc[na][e] = 0.f;
    float m0 = -1e30f, m1 = -1e30f, l0 = 0.f, l1 = 0.f;

    int r0 = w * 16 + gid, r1 = r0 + 8;
    int i0 = qs + r0, i1 = qs + r1;
    int cq = qs >> 5;                       // first diagonal chunk
    int clo = (cq >= 16) ? cq - 16 : 0;
    int chi = cq + 3;                       // covers rows qs..qs+127

    for (int c = clo; c <= chi; c++) {
        int kstart = c * 32;
        __syncthreads();
        // stage K chunk 32x256 (tf32)
        for (int i = tid; i < 32 * 64; i += 256) {
            int r = i >> 6, c4 = i & 63;
            float4 v = *reinterpret_cast<const float4*>(
                &g_k[(size_t)(b * S_LEN + kstart + r) * D_HEAD + c4 * 4]);
            float* d = &Ks[r * KS_STR + c4 * 4];
            d[0] = tf(v.x); d[1] = tf(v.y); d[2] = tf(v.z); d[3] = tf(v.w);
        }
        // stage V^T chunk 256x32 (tf32)
        for (int i = tid; i < 256 * 8; i += 256) {
            int dd = i >> 3, j4 = i & 7;
            float4 v = *reinterpret_cast<const float4*>(
                &g_vT[(size_t)dd * BS_TOT + b * S_LEN + kstart + j4 * 4]);
            float* d = &VsT[dd * VT_STR + j4 * 4];
            d[0] = tf(v.x); d[1] = tf(v.y); d[2] = tf(v.z); d[3] = tf(v.w);
        }
        __syncthreads();

        // phase 1: S = Q @ K^T  (128 rows x 32 keys; 16 rows per warp)
        float s[4][4];
        #pragma unroll
        for (int na = 0; na < 4; na++)
            #pragma unroll
            for (int e = 0; e < 4; e++) s[na][e] = 0.f;

        #pragma unroll
        for (int ks = 0; ks < 32; ks++) {
            int kk = ks * 8;
            const float* ab = &Qs[r0 * QS_STR + kk];
            uint32_t a0 = __float_as_uint(ab[tig]);
            uint32_t a1 = __float_as_uint(ab[8 * QS_STR + tig]);
            uint32_t a2 = __float_as_uint(ab[tig + 4]);
            uint32_t a3 = __float_as_uint(ab[8 * QS_STR + tig + 4]);
            #pragma unroll
            for (int na = 0; na < 4; na++) {
                const float* bb = &Ks[(na * 8 + gid) * KS_STR + kk];
                uint32_t b0 = __float_as_uint(bb[tig]);
                uint32_t b1 = __float_as_uint(bb[tig + 4]);
                MMA8(s[na], a0, a1, a2, a3, b0, b1);
            }
        }

        // mask: diagonal chunks (j > i) and trailing window-edge chunks (i-j > WIN)
        if (c >= cq || kstart < qs - 384) {
            #pragma unroll
            for (int na = 0; na < 4; na++) {
                int j0 = kstart + na * 8 + 2 * tig;
                #pragma unroll
                for (int e = 0; e < 4; e++) {
                    int j = j0 + (e & 1);
                    int i = (e < 2) ? i0 : i1;
                    if (j > i || i - j > WIN) s[na][e] = -1e30f;
                }
            }
        }

        // row max over 32 keys (8 in-thread + quad shfl)
        float mx0 = -1e30f, mx1 = -1e30f;
        #pragma unroll
        for (int na = 0; na < 4; na++) {
            mx0 = fmaxf(mx0, fmaxf(s[na][0], s[na][1]));
            mx1 = fmaxf(mx1, fmaxf(s[na][2], s[na][3]));
        }
        mx0 = fmaxf(mx0, __shfl_xor_sync(0xffffffffu, mx0, 1));
        mx0 = fmaxf(mx0, __shfl_xor_sync(0xffffffffu, mx0, 2));
        mx1 = fmaxf(mx1, __shfl_xor_sync(0xffffffffu, mx1, 1));
        mx1 = fmaxf(mx1, __shfl_xor_sync(0xffffffffu, mx1, 2));

        float mn0 = fmaxf(m0, mx0), mn1 = fmaxf(m1, mx1);
        float al0 = __expf(m0 - mn0), al1 = __expf(m1 - mn1);
        m0 = mn0; m1 = mn1;

        float sum0 = 0.f, sum1 = 0.f;
        #pragma unroll
        for (int na = 0; na < 4; na++) {
            float p00 = __expf(s[na][0] - m0);
            float p01 = __expf(s[na][1] - m0);
            float p10 = __expf(s[na][2] - m1);
            float p11 = __expf(s[na][3] - m1);
            sum0 += p00 + p01; sum1 += p10 + p11;
            int cc = na * 8 + 2 * tig;
            *reinterpret_cast<float2*>(&Ps[r0 * PS_STR + cc]) =
                make_float2(__uint_as_float(f2tf32(p00)), __uint_as_float(f2tf32(p01)));
            *reinterpret_cast<float2*>(&Ps[r1 * PS_STR + cc]) =
                make_float2(__uint_as_float(f2tf32(p10)), __uint_as_float(f2tf32(p11)));
        }
        sum0 += __shfl_xor_sync(0xffffffffu, sum0, 1);
        sum0 += __shfl_xor_sync(0xffffffffu, sum0, 2);
        sum1 += __shfl_xor_sync(0xffffffffu, sum1, 1);
        sum1 += __shfl_xor_sync(0xffffffffu, sum1, 2);
        l0 = l0 * al0 + sum0;
        l1 = l1 * al1 + sum1;

        #pragma unroll
        for (int na = 0; na < 32; na++) {
            acc[na][0] *= al0; acc[na][1] *= al0;
            acc[na][2] *= al1; acc[na][3] *= al1;
        }
        __syncwarp();

        // phase 2: O += P @ V  (k = 32 keys, n = 256 dims)
        #pragma unroll
        for (int ks = 0; ks < 4; ks++) {
            int kk = ks * 8;
            const float* ab = &Ps[r0 * PS_STR + kk];
            uint32_t a0 = __float_as_uint(ab[tig]);
            uint32_t a1 = __float_as_uint(ab[8 * PS_STR + tig]);
            uint32_t a2 = __float_as_uint(ab[tig + 4]);
            uint32_t a3 = __float_as_uint(ab[8 * PS_STR + tig + 4]);
            #pragma unroll
            for (int na = 0; na < 32; na++) {
                const float* bb = &VsT[(na * 8 + gid) * VT_STR + kk];
                uint32_t b0 = __float_as_uint(bb[tig]);
                uint32_t b1 = __float_as_uint(bb[tig + 4]);
                MMA8(acc[na], a0, a1, a2, a3, b0, b1);
            }
        }
    }

    float inv0 = 1.0f / l0, inv1 = 1.0f / l1;
    size_t base0 = (size_t)(b * S_LEN + qs + r0) * HD + h * D_HEAD;
    size_t base1 = (size_t)(b * S_LEN + qs + r1) * HD + h * D_HEAD;
    #pragma unroll
    for (int na = 0; na < 32; na++) {
        int cc = na * 8 + 2 * tig;
        *reinterpret_cast<float2*>(&g_ao[base0 + cc]) = make_float2(acc[na][0] * inv0, acc[na][1] * inv0);
        *reinterpret_cast<float2*>(&g_ao[base1 + cc]) = make_float2(acc[na][2] * inv1, acc[na][3] * inv1);
    }
}

// ---------------- launch ----------------
extern "C" void kernel_launch(void* const* d_in, const int* in_sizes, int n_in,
                              void* d_out, int out_size) {
    const float* x    = (const float*)d_in[0];
    const float* cosb = (const float*)d_in[1];
    const float* sinb = (const float*)d_in[2];
    const float* Wq   = (const float*)d_in[3];
    const float* Wk   = (const float*)d_in[4];
    const float* Wv   = (const float*)d_in[5];
    const float* Wo   = (const float*)d_in[6];
    const float* qw   = (const float*)d_in[7];
    const float* kw   = (const float*)d_in[8];
    float* out = (float*)d_out;

    static int smem_set = 0;
    if (!smem_set) {
        cudaFuncSetAttribute(attn_mma, cudaFuncAttributeMaxDynamicSharedMemorySize, ATTN_SMEM);
        cudaFuncSetAttribute(qkv_gemm, cudaFuncAttributeMaxDynamicSharedMemorySize, GEMM_SMEM);
        cudaFuncSetAttribute(wo_gemm,  cudaFuncAttributeMaxDynamicSharedMemorySize, GEMM_SMEM);
        smem_set = 1;
    }

    qkv_gemm<<<dim3(12, BS_TOT / 128), 256, GEMM_SMEM>>>(x, Wq, Wk, Wv);

    norm_rope_kernel<<<dim3(BS_TOT, H_Q + 1), 128>>>(cosb, sinb, qw, kw);

    attn_mma<<<dim3(S_LEN / 128, NB, H_Q), 256, ATTN_SMEM>>>();

    wo_gemm<<<dim3(E_DIM / 128, BS_TOT / 128), 256, GEMM_SMEM>>>(Wo, out);
}